// round 16
// baseline (speedup 1.0000x reference)
#include <cuda_runtime.h>
#include <cuda_fp16.h>

#define M_ROWS 8192
#define N_CLASSES 256
#define DIM 128
#define BM 64
#define BN 128
#define NTILES 256            // (8192/64) * (256/128) = total CTAs

// ---------------- scratch (__device__ globals; allocation-free rule) -------
__device__ __align__(16) __half g_hp[N_CLASSES * DIM];
__device__ float g_pnorm[N_CLASSES];
__device__ volatile int g_done;     // zero-init; last passer resets each call
__device__ int g_passed;

static __device__ __forceinline__ unsigned smem_u32(const void* p) {
    return (unsigned)__cvta_generic_to_shared(p);
}

#define LDM4(d0, d1, d2, d3, a)                                              \
    asm volatile("ldmatrix.sync.aligned.m8n8.x4.shared.b16 {%0,%1,%2,%3}, [%4];" \
                 : "=r"(d0), "=r"(d1), "=r"(d2), "=r"(d3) : "r"(a))

#define MMA16816(c0, c1, c2, c3, a0, a1, a2, a3, b0, b1)                     \
    asm volatile("mma.sync.aligned.m16n8k16.row.col.f32.f16.f16.f32 "        \
                 "{%0,%1,%2,%3}, {%4,%5,%6,%7}, {%8,%9}, {%0,%1,%2,%3};"     \
                 : "+f"(c0), "+f"(c1), "+f"(c2), "+f"(c3)                    \
                 : "r"(a0), "r"(a1), "r"(a2), "r"(a3), "r"(b0), "r"(b1))

#define CP_ASYNC16(dst, src)                                                 \
    asm volatile("cp.async.cg.shared.global [%0], [%1], 16;"                 \
                 :: "r"(dst), "l"(src))

// Shared-memory layout (bytes), total 54272; x2 CTAs/SM = 108544 <= 228KB:
//   [0,     16384)  hA      64x128 fp16 (x tile)
//   [16384, 49152)  hB      128x128 fp16 (B tile)
//   [49152, 53504)  xpart   64x17 f32  -- pre-barrier reused by proto:
//       [49152, 53248) part2[8][128] f32
//       [53248, 53280) cntw[8] int
//       [53280, 53296) red[4] f32
//   [53504, 53760)  xnorm   64 f32
//   [53760, 54272)  pnorm   128 f32
#define SMEM_TOTAL 54272

__global__ void __launch_bounds__(256, 2)
fused_kernel(const float* __restrict__ x,
             const float* __restrict__ support,
             const int* __restrict__ labels,
             float* __restrict__ out, int S) {
    extern __shared__ char smraw[];
    __half* hA      = (__half*)(smraw);
    __half* hB      = (__half*)(smraw + 16384);
    float*  xpart   = (float*) (smraw + 49152);   // [64][17]
    float*  part2   = (float*) (smraw + 49152);   // proto: [8][128]
    int*    cntw    = (int*)   (smraw + 53248);   // proto: [8]
    float*  red     = (float*) (smraw + 53280);   // proto: [4]
    float*  xnorm_s = (float*) (smraw + 53504);   // [64]
    float*  pnorm_s = (float*) (smraw + 53760);   // [128]

    int tid  = threadIdx.x;
    int lane = tid & 31;
    int wid  = tid >> 5;
    int m0  = blockIdx.x * BM;
    int n0  = blockIdx.y * BN;
    int cls = blockIdx.y * 128 + blockIdx.x;      // one class per CTA

    // ===== Phase 0: issue ALL x loads at t=0 (latency drains under proto) ==
    float4 xv[8];
    {
        const float4* gx = (const float4*)(x + (size_t)m0 * DIM);
        #pragma unroll
        for (int i = 0; i < 4; i++) {
            int idx = tid + i * 256;
            int row = idx >> 4, c = idx & 15;
            xv[2 * i]     = __ldg(&gx[row * 32 + c * 2]);
            xv[2 * i + 1] = __ldg(&gx[row * 32 + c * 2 + 1]);
        }
    }

    // ===== Phase 1: prototype via single-pass ballot-gather ================
    // Warp w owns rows [512w, 512w+512). One coalesced label pass; per match
    // the whole warp loads the row (float4/lane = dims [4*lane,4*lane+4)).
    {
        const int4* L4 = (const int4*)labels;
        int n4 = S >> 2;                    // 1024
        const float4* sup4 = (const float4*)support;

        float4 pacc = make_float4(0.f, 0.f, 0.f, 0.f);
        int wcnt = 0;

        #pragma unroll
        for (int k = 0; k < 4; k++) {
            int idx = wid * 128 + k * 32 + lane;
            int4 v = (idx < n4) ? __ldg(&L4[idx]) : make_int4(-1, -1, -1, -1);
            int labs[4] = {v.x, v.y, v.z, v.w};
            #pragma unroll
            for (int e = 0; e < 4; e++) {
                unsigned mask = __ballot_sync(0xffffffffu, labs[e] == cls);
                wcnt += __popc(mask);
                while (mask) {
                    int l = __ffs(mask) - 1;
                    mask &= mask - 1;
                    int row = ((wid * 128 + k * 32 + l) << 2) + e;
                    float4 val = __ldg(&sup4[(size_t)row * 32 + lane]);
                    pacc.x += val.x; pacc.y += val.y;
                    pacc.z += val.z; pacc.w += val.w;
                }
            }
        }

        ((float4*)part2)[wid * 32 + lane] = pacc;
        if (lane == 0) cntw[wid] = wcnt;
        __syncthreads();

        if (tid < DIM) {
            float s = 0.f;
            #pragma unroll
            for (int w = 0; w < 8; w++) s += part2[w * DIM + tid];
            int total = 0;
            #pragma unroll
            for (int w = 0; w < 8; w++) total += cntw[w];

            float v = s / fmaxf((float)total, 1.0f);
            g_hp[cls * DIM + tid] = __float2half_rn(v);

            float q = v * v;
            #pragma unroll
            for (int o = 16; o > 0; o >>= 1)
                q += __shfl_xor_sync(0xffffffffu, q, o);
            if (lane == 0) red[wid] = q;
        }
        __syncthreads();
        if (tid == 0) g_pnorm[cls] = red[0] + red[1] + red[2] + red[3];
    }

    // ================= Arrive at grid barrier EARLY ========================
    __syncthreads();
    if (tid == 0) {
        __threadfence();                      // publish g_hp/g_pnorm
        atomicAdd((int*)&g_done, 1);
    }

    // ===== Phase 2: convert prefetched x regs -> smem; hides barrier wait ==
    {
        uint4* shA = (uint4*)hA;
        #pragma unroll
        for (int i = 0; i < 4; i++) {
            int idx = tid + i * 256;
            int row = idx >> 4, c = idx & 15;
            float4 v0 = xv[2 * i];
            float4 v1 = xv[2 * i + 1];

            union { __half2 q[4]; uint4 u; } H;
            H.q[0] = __floats2half2_rn(v0.x, v0.y);
            H.q[1] = __floats2half2_rn(v0.z, v0.w);
            H.q[2] = __floats2half2_rn(v1.x, v1.y);
            H.q[3] = __floats2half2_rn(v1.z, v1.w);

            int sw = c ^ (row & 7);
            shA[row * 16 + sw] = H.u;

            xpart[row * 17 + c] =
                  v0.x * v0.x + v0.y * v0.y + v0.z * v0.z + v0.w * v0.w
                + v1.x * v1.x + v1.y * v1.y + v1.z * v1.z + v1.w * v1.w;
        }
    }
    __syncthreads();
    if (tid < BM) {
        float s = 0.0f;
        #pragma unroll
        for (int c = 0; c < 16; c++) s += xpart[tid * 17 + c];
        xnorm_s[tid] = s;
    }

    // ================= Spin (most CTAs find it already complete) ===========
    if (tid == 0) {
        while (g_done < NTILES) __nanosleep(32);
        int p = atomicAdd(&g_passed, 1);
        if (p == NTILES - 1) { g_passed = 0; g_done = 0; }
    }
    __syncthreads();

    // ================= Phase 3: B tile + pnorm, then MMA (proven GEMM) =====
    {
        const uint4* ghB = (const uint4*)(g_hp + (size_t)n0 * DIM);
        unsigned sB = smem_u32(hB);
        #pragma unroll
        for (int i = 0; i < 8; i++) {         // 2048 chunks = BN*DIM*2/16
            int idx = tid + i * 256;
            int row = idx >> 4, c = idx & 15;
            int sw = c ^ (row & 7);
            CP_ASYNC16(sB + (unsigned)(row * 16 + sw) * 16, ghB + idx);
        }
        asm volatile("cp.async.commit_group;");
    }
    if (tid < BN) pnorm_s[tid] = __ldcg(&g_pnorm[n0 + tid]);

    asm volatile("cp.async.wait_group 0;");
    __syncthreads();

    int wm = wid & 1;         // m, 32 rows each
    int wn = wid >> 1;        // n, 32 cols each
    int grp = lane >> 3, lr = lane & 7;

    int rowA[2], keyA[2];
    #pragma unroll
    for (int ms = 0; ms < 2; ms++) {
        rowA[ms] = wm * 32 + ms * 16 + lr + ((grp & 1) << 3);
        keyA[ms] = rowA[ms] & 7;
    }
    int cAadd = grp >> 1;
    int rowB[2], keyB[2];
    #pragma unroll
    for (int np = 0; np < 2; np++) {
        rowB[np] = wn * 32 + np * 16 + lr + ((grp >> 1) << 3);
        keyB[np] = rowB[np] & 7;
    }
    int cBadd = grp & 1;

    unsigned baseHA = smem_u32(hA);
    unsigned baseHB = smem_u32(hB);
    unsigned offA[2], offB[2];
    #pragma unroll
    for (int i = 0; i < 2; i++) { offA[i] = rowA[i] * 256; offB[i] = rowB[i] * 256; }

    float acc[2][4][4];
    #pragma unroll
    for (int i = 0; i < 2; i++)
        #pragma unroll
        for (int j = 0; j < 4; j++)
            #pragma unroll
            for (int k = 0; k < 4; k++) acc[i][j][k] = 0.0f;

    #pragma unroll
    for (int ks = 0; ks < 8; ks++) {
        int kc = ks * 2;
        unsigned ah[2][4], bh[2][4];
        #pragma unroll
        for (int ms = 0; ms < 2; ms++) {
            unsigned sw = ((unsigned)((kc + cAadd) ^ keyA[ms])) << 4;
            LDM4(ah[ms][0], ah[ms][1], ah[ms][2], ah[ms][3], baseHA + offA[ms] + sw);
        }
        #pragma unroll
        for (int np = 0; np < 2; np++) {
            unsigned sw = ((unsigned)((kc + cBadd) ^ keyB[np])) << 4;
            LDM4(bh[np][0], bh[np][1], bh[np][2], bh[np][3], baseHB + offB[np] + sw);
        }
        #pragma unroll
        for (int ms = 0; ms < 2; ms++) {
            #pragma unroll
            for (int ns = 0; ns < 4; ns++) {
                int np = ns >> 1, o = (ns & 1) * 2;
                float* c = acc[ms][ns];
                MMA16816(c[0], c[1], c[2], c[3],
                         ah[ms][0], ah[ms][1], ah[ms][2], ah[ms][3],
                         bh[np][o], bh[np][o + 1]);
            }
        }
    }

    // ---- epilogue: out = 2*dot - xnorm - pnorm ----
    int qrow = lane >> 2;
    int qcol = (lane & 3) * 2;
    #pragma unroll
    for (int ms = 0; ms < 2; ms++) {
        int lrow = wm * 32 + ms * 16 + qrow;
        int mrow = m0 + lrow;
        float xn0 = xnorm_s[lrow];
        float xn1 = xnorm_s[lrow + 8];
        #pragma unroll
        for (int ns = 0; ns < 4; ns++) {
            int nl = wn * 32 + ns * 8 + qcol;
            int n  = n0 + nl;
            float pn0 = pnorm_s[nl];
            float pn1 = pnorm_s[nl + 1];
            float* c = acc[ms][ns];
            float2 o0 = make_float2(2.0f * c[0] - xn0 - pn0,
                                    2.0f * c[1] - xn0 - pn1);
            float2 o1 = make_float2(2.0f * c[2] - xn1 - pn0,
                                    2.0f * c[3] - xn1 - pn1);
            *(float2*)&out[(size_t)mrow * N_CLASSES + n] = o0;
            *(float2*)&out[(size_t)(mrow + 8) * N_CLASSES + n] = o1;
        }
    }
}

// ---------------------------------------------------------------------------
extern "C" void kernel_launch(void* const* d_in, const int* in_sizes, int n_in,
                              void* d_out, int out_size) {
    const float* x       = (const float*)d_in[0];
    const float* support = (const float*)d_in[1];
    const int*   labels  = (const int*)d_in[2];
    float* out = (float*)d_out;

    int S = in_sizes[2];  // 4096

    cudaFuncSetAttribute(fused_kernel,
                         cudaFuncAttributeMaxDynamicSharedMemorySize, SMEM_TOTAL);
    fused_kernel<<<dim3(M_ROWS / BM, N_CLASSES / BN), 256, SMEM_TOTAL>>>(
        x, support, labels, out, S);
}

// round 17
// speedup vs baseline: 1.0226x; 1.0226x over previous
#include <cuda_runtime.h>
#include <cuda_fp16.h>

#define M_ROWS 8192
#define N_CLASSES 256
#define DIM 128
#define BM 64
#define BN 128
#define NGROUP 128            // CTAs per barrier group (one per blockIdx.y)

// ---------------- scratch (__device__ globals; allocation-free rule) -------
__device__ __align__(16) __half g_hp[N_CLASSES * DIM];
__device__ float g_pnorm[N_CLASSES];
__device__ volatile int g_done2[2];   // zero-init; per-group; reset by last passer
__device__ int g_passed2[2];

static __device__ __forceinline__ unsigned smem_u32(const void* p) {
    return (unsigned)__cvta_generic_to_shared(p);
}

#define LDM4(d0, d1, d2, d3, a)                                              \
    asm volatile("ldmatrix.sync.aligned.m8n8.x4.shared.b16 {%0,%1,%2,%3}, [%4];" \
                 : "=r"(d0), "=r"(d1), "=r"(d2), "=r"(d3) : "r"(a))

#define MMA16816(c0, c1, c2, c3, a0, a1, a2, a3, b0, b1)                     \
    asm volatile("mma.sync.aligned.m16n8k16.row.col.f32.f16.f16.f32 "        \
                 "{%0,%1,%2,%3}, {%4,%5,%6,%7}, {%8,%9}, {%0,%1,%2,%3};"     \
                 : "+f"(c0), "+f"(c1), "+f"(c2), "+f"(c3)                    \
                 : "r"(a0), "r"(a1), "r"(a2), "r"(a3), "r"(b0), "r"(b1))

#define CP_ASYNC16(dst, src)                                                 \
    asm volatile("cp.async.cg.shared.global [%0], [%1], 16;"                 \
                 :: "r"(dst), "l"(src))

// Shared-memory layout (bytes), total 54272; x2 CTAs/SM = 108544 <= 228KB:
//   [0,     16384)  hA      64x128 fp16 (x tile)
//   [16384, 49152)  hB      128x128 fp16 (B tile)  -- pre-barrier reused by
//                   proto scratch: list[4096] / part[2][128] / wbase[9] / red[4]
//   [49152, 53504)  xpart   64x17 f32
//   [53504, 53760)  xnorm   64 f32
//   [53760, 54272)  pnorm   128 f32
#define SMEM_TOTAL 54272

__global__ void __launch_bounds__(256, 2)
fused_kernel(const float* __restrict__ x,
             const float* __restrict__ support,
             const int* __restrict__ labels,
             float* __restrict__ out, int S) {
    extern __shared__ char smraw[];
    __half* hA      = (__half*)(smraw);
    __half* hB      = (__half*)(smraw + 16384);
    int*    list    = (int*)   (smraw + 16384);
    float*  part    = (float*) (smraw + 32768);   // [2][128]
    int*    wbase   = (int*)   (smraw + 33792);   // [9]
    float*  red     = (float*) (smraw + 33828);   // [4]
    float*  xpart   = (float*) (smraw + 49152);   // [64][17]
    float*  xnorm_s = (float*) (smraw + 53504);   // [64]
    float*  pnorm_s = (float*) (smraw + 53760);   // [128]

    int tid  = threadIdx.x;
    int lane = tid & 31;
    int wid  = tid >> 5;
    int m0  = blockIdx.x * BM;
    int by  = blockIdx.y;
    int n0  = by * BN;
    int cls = by * 128 + blockIdx.x;      // one class per CTA, group = by

    // ===== Phase 0: issue ALL x loads at t=0 (latency drains under proto) ==
    float4 xv[8];
    {
        const float4* gx = (const float4*)(x + (size_t)m0 * DIM);
        #pragma unroll
        for (int i = 0; i < 4; i++) {
            int idx = tid + i * 256;
            int row = idx >> 4, c = idx & 15;
            xv[2 * i]     = __ldg(&gx[row * 32 + c * 2]);
            xv[2 * i + 1] = __ldg(&gx[row * 32 + c * 2 + 1]);
        }
    }

    // ================= Phase 1: prototype for class `cls` (R15 proto) ======
    {
        const int4* L4 = (const int4*)labels;
        int n4 = S >> 2;                    // 1024

        int cnt = 0;
        #pragma unroll
        for (int i = 0; i < 4; i++) {
            int idx = tid + i * 256;
            if (idx < n4) {
                int4 v = __ldg(&L4[idx]);
                cnt += (v.x == cls) + (v.y == cls) + (v.z == cls) + (v.w == cls);
            }
        }

        int inc = cnt;
        #pragma unroll
        for (int o = 1; o < 32; o <<= 1) {
            int t = __shfl_up_sync(0xffffffffu, inc, o);
            if (lane >= o) inc += t;
        }
        if (lane == 31) wbase[wid + 1] = inc;
        if (tid == 0) wbase[0] = 0;
        __syncthreads();
        if (tid == 0)
            #pragma unroll
            for (int w = 1; w <= 8; w++) wbase[w] += wbase[w - 1];
        __syncthreads();

        int pos = wbase[wid] + inc - cnt;
        #pragma unroll
        for (int i = 0; i < 4; i++) {
            int idx = tid + i * 256;
            if (idx < n4) {
                int4 v = __ldg(&L4[idx]);
                int r = idx * 4;
                if (v.x == cls) list[pos++] = r;
                if (v.y == cls) list[pos++] = r + 1;
                if (v.z == cls) list[pos++] = r + 2;
                if (v.w == cls) list[pos++] = r + 3;
            }
        }
        __syncthreads();

        int total = wbase[8];

        // gather: (dim, half), MLP 8
        {
            int d    = tid & 127;
            int half = tid >> 7;
            float s = 0.0f;
            int i = half;
            for (; i + 14 < total; i += 16) {
                float a0 = __ldg(&support[(size_t)list[i]      * DIM + d]);
                float a1 = __ldg(&support[(size_t)list[i + 2]  * DIM + d]);
                float a2 = __ldg(&support[(size_t)list[i + 4]  * DIM + d]);
                float a3 = __ldg(&support[(size_t)list[i + 6]  * DIM + d]);
                float a4 = __ldg(&support[(size_t)list[i + 8]  * DIM + d]);
                float a5 = __ldg(&support[(size_t)list[i + 10] * DIM + d]);
                float a6 = __ldg(&support[(size_t)list[i + 12] * DIM + d]);
                float a7 = __ldg(&support[(size_t)list[i + 14] * DIM + d]);
                s += a0; s += a1; s += a2; s += a3;
                s += a4; s += a5; s += a6; s += a7;
            }
            for (; i < total; i += 2)
                s += __ldg(&support[(size_t)list[i] * DIM + d]);
            part[half * DIM + d] = s;
        }
        __syncthreads();

        if (tid < DIM) {
            float cntf = fmaxf((float)total, 1.0f);
            float v = (part[tid] + part[DIM + tid]) / cntf;
            g_hp[cls * DIM + tid] = __float2half_rn(v);

            float q = v * v;
            #pragma unroll
            for (int o = 16; o > 0; o >>= 1)
                q += __shfl_xor_sync(0xffffffffu, q, o);
            if (lane == 0) red[wid] = q;
        }
        __syncthreads();
        if (tid == 0) g_pnorm[cls] = red[0] + red[1] + red[2] + red[3];
    }

    // ========= Arrive EARLY at the per-group (128-CTA) barrier =============
    __syncthreads();
    if (tid == 0) {
        __threadfence();                      // publish g_hp/g_pnorm
        atomicAdd((int*)&g_done2[by], 1);
    }

    // ===== Phase 2: convert prefetched x regs -> smem; hides barrier wait ==
    {
        uint4* shA = (uint4*)hA;
        #pragma unroll
        for (int i = 0; i < 4; i++) {
            int idx = tid + i * 256;
            int row = idx >> 4, c = idx & 15;
            float4 v0 = xv[2 * i];
            float4 v1 = xv[2 * i + 1];

            union { __half2 q[4]; uint4 u; } H;
            H.q[0] = __floats2half2_rn(v0.x, v0.y);
            H.q[1] = __floats2half2_rn(v0.z, v0.w);
            H.q[2] = __floats2half2_rn(v1.x, v1.y);
            H.q[3] = __floats2half2_rn(v1.z, v1.w);

            int sw = c ^ (row & 7);
            shA[row * 16 + sw] = H.u;

            xpart[row * 17 + c] =
                  v0.x * v0.x + v0.y * v0.y + v0.z * v0.z + v0.w * v0.w
                + v1.x * v1.x + v1.y * v1.y + v1.z * v1.z + v1.w * v1.w;
        }
    }
    __syncthreads();
    if (tid < BM) {
        float s = 0.0f;
        #pragma unroll
        for (int c = 0; c < 16; c++) s += xpart[tid * 17 + c];
        xnorm_s[tid] = s;
    }

    // ================= Spin on our group's counter ==========================
    if (tid == 0) {
        while (g_done2[by] < NGROUP) __nanosleep(32);
        int p = atomicAdd(&g_passed2[by], 1);
        if (p == NGROUP - 1) { g_passed2[by] = 0; g_done2[by] = 0; }
    }
    __syncthreads();

    // ===== Phase 3: B tile in TWO k-half cp.async groups + pnorm ===========
    {
        const uint4* ghB = (const uint4*)(g_hp + (size_t)n0 * DIM);
        unsigned sB = smem_u32(hB);
        // group 1: k-chunks 0..7 of every row (1024 chunks)
        #pragma unroll
        for (int i = 0; i < 4; i++) {
            int t = tid + i * 256;
            int row = t >> 3, c = t & 7;          // c in [0,8)
            int sw = c ^ (row & 7);               // stays in [0,8)
            CP_ASYNC16(sB + (unsigned)(row * 16 + sw) * 16, ghB + row * 16 + c);
        }
        asm volatile("cp.async.commit_group;");
        // group 2: k-chunks 8..15 (1024 chunks)
        #pragma unroll
        for (int i = 0; i < 4; i++) {
            int t = tid + i * 256;
            int row = t >> 3, c = (t & 7) + 8;    // c in [8,16)
            int sw = c ^ (row & 7);               // stays in [8,16)
            CP_ASYNC16(sB + (unsigned)(row * 16 + sw) * 16, ghB + row * 16 + c);
        }
        asm volatile("cp.async.commit_group;");
    }
    if (tid < BN) pnorm_s[tid] = __ldcg(&g_pnorm[n0 + tid]);

    // wait for first k-half of B
    asm volatile("cp.async.wait_group 1;");
    __syncthreads();

    int wm = wid & 1;         // m, 32 rows each
    int wn = wid >> 1;        // n, 32 cols each
    int grp = lane >> 3, lr = lane & 7;

    int rowA[2], keyA[2];
    #pragma unroll
    for (int ms = 0; ms < 2; ms++) {
        rowA[ms] = wm * 32 + ms * 16 + lr + ((grp & 1) << 3);
        keyA[ms] = rowA[ms] & 7;
    }
    int cAadd = grp >> 1;
    int rowB[2], keyB[2];
    #pragma unroll
    for (int np = 0; np < 2; np++) {
        rowB[np] = wn * 32 + np * 16 + lr + ((grp >> 1) << 3);
        keyB[np] = rowB[np] & 7;
    }
    int cBadd = grp & 1;

    unsigned baseHA = smem_u32(hA);
    unsigned baseHB = smem_u32(hB);
    unsigned offA[2], offB[2];
    #pragma unroll
    for (int i = 0; i < 2; i++) { offA[i] = rowA[i] * 256; offB[i] = rowB[i] * 256; }

    float acc[2][4][4];
    #pragma unroll
    for (int i = 0; i < 2; i++)
        #pragma unroll
        for (int j = 0; j < 4; j++)
            #pragma unroll
            for (int k = 0; k < 4; k++) acc[i][j][k] = 0.0f;

    // ---- k-steps 0..3 (uses k-chunks 0..7 only: kc+cadd <= 7) ----
    #pragma unroll
    for (int ks = 0; ks < 4; ks++) {
        int kc = ks * 2;
        unsigned ah[2][4], bh[2][4];
        #pragma unroll
        for (int ms = 0; ms < 2; ms++) {
            unsigned sw = ((unsigned)((kc + cAadd) ^ keyA[ms])) << 4;
            LDM4(ah[ms][0], ah[ms][1], ah[ms][2], ah[ms][3], baseHA + offA[ms] + sw);
        }
        #pragma unroll
        for (int np = 0; np < 2; np++) {
            unsigned sw = ((unsigned)((kc + cBadd) ^ keyB[np])) << 4;
            LDM4(bh[np][0], bh[np][1], bh[np][2], bh[np][3], baseHB + offB[np] + sw);
        }
        #pragma unroll
        for (int ms = 0; ms < 2; ms++) {
            #pragma unroll
            for (int ns = 0; ns < 4; ns++) {
                int np = ns >> 1, o = (ns & 1) * 2;
                float* c = acc[ms][ns];
                MMA16816(c[0], c[1], c[2], c[3],
                         ah[ms][0], ah[ms][1], ah[ms][2], ah[ms][3],
                         bh[np][o], bh[np][o + 1]);
            }
        }
    }

    // wait for second k-half of B
    asm volatile("cp.async.wait_group 0;");
    __syncthreads();

    // ---- k-steps 4..7 ----
    #pragma unroll
    for (int ks = 4; ks < 8; ks++) {
        int kc = ks * 2;
        unsigned ah[2][4], bh[2][4];
        #pragma unroll
        for (int ms = 0; ms < 2; ms++) {
            unsigned sw = ((unsigned)((kc + cAadd) ^ keyA[ms])) << 4;
            LDM4(ah[ms][0], ah[ms][1], ah[ms][2], ah[ms][3], baseHA + offA[ms] + sw);
        }
        #pragma unroll
        for (int np = 0; np < 2; np++) {
            unsigned sw = ((unsigned)((kc + cBadd) ^ keyB[np])) << 4;
            LDM4(bh[np][0], bh[np][1], bh[np][2], bh[np][3], baseHB + offB[np] + sw);
        }
        #pragma unroll
        for (int ms = 0; ms < 2; ms++) {
            #pragma unroll
            for (int ns = 0; ns < 4; ns++) {
                int np = ns >> 1, o = (ns & 1) * 2;
                float* c = acc[ms][ns];
                MMA16816(c[0], c[1], c[2], c[3],
                         ah[ms][0], ah[ms][1], ah[ms][2], ah[ms][3],
                         bh[np][o], bh[np][o + 1]);
            }
        }
    }

    // ---- epilogue: out = 2*dot - xnorm - pnorm ----
    int qrow = lane >> 2;
    int qcol = (lane & 3) * 2;
    #pragma unroll
    for (int ms = 0; ms < 2; ms++) {
        int lrow = wm * 32 + ms * 16 + qrow;
        int mrow = m0 + lrow;
        float xn0 = xnorm_s[lrow];
        float xn1 = xnorm_s[lrow + 8];
        #pragma unroll
        for (int ns = 0; ns < 4; ns++) {
            int nl = wn * 32 + ns * 8 + qcol;
            int n  = n0 + nl;
            float pn0 = pnorm_s[nl];
            float pn1 = pnorm_s[nl + 1];
            float* c = acc[ms][ns];
            float2 o0 = make_float2(2.0f * c[0] - xn0 - pn0,
                                    2.0f * c[1] - xn0 - pn1);
            float2 o1 = make_float2(2.0f * c[2] - xn1 - pn0,
                                    2.0f * c[3] - xn1 - pn1);
            *(float2*)&out[(size_t)mrow * N_CLASSES + n] = o0;
            *(float2*)&out[(size_t)(mrow + 8) * N_CLASSES + n] = o1;
        }
    }
}

// ---------------------------------------------------------------------------
extern "C" void kernel_launch(void* const* d_in, const int* in_sizes, int n_in,
                              void* d_out, int out_size) {
    const float* x       = (const float*)d_in[0];
    const float* support = (const float*)d_in[1];
    const int*   labels  = (const int*)d_in[2];
    float* out = (float*)d_out;

    int S = in_sizes[2];  // 4096

    cudaFuncSetAttribute(fused_kernel,
                         cudaFuncAttributeMaxDynamicSharedMemorySize, SMEM_TOTAL);
    fused_kernel<<<dim3(M_ROWS / BM, N_CLASSES / BN), 256, SMEM_TOTAL>>>(
        x, support, labels, out, S);
}